// round 10
// baseline (speedup 1.0000x reference)
#include <cuda_runtime.h>

// ImprovedRNN (LSTM) B=256, T=1024, I=64, H=25, O=64, fp32.
// Gate order (PyTorch): i, f, g, o = rows 0..24, 25..49, 50..74, 75..99.
//
// prep_kernel: packs weight pairs into a __device__ staging buffer; one
//   cudaMemcpyToSymbolAsync (D2D, graph-capturable) moves it to __constant__.
//   Constant-port reads (uniform LDCU) take the weight traffic OFF the L1
//   crossbar, which R7 proved is the gates/fc bottleneck (bytes, not instrs).
// gates_kernel: one thread per (b,t) row, x packed {xi,xi} in regs, weights
//   from constant. Output g_gates[row*25+j] = float4{i,f,g,o}.
// lstm_kernel: one warp per TWO batch elements (interleaved sequences fill
//   dependency stalls), shuffle-based h broadcast (R7 showed smem is worse),
//   single-MUFU tanh.approx for ALL activations, 4-deep prefetch per seq.
// fc_kernel: out = hs @ W_fc^T + b_fc, weights from constant.

static constexpr int Bb = 256;
static constexpr int Tt = 1024;
static constexpr int Ii = 64;
static constexpr int Hh = 25;
static constexpr int Gg = 4 * Hh;   // 100
static constexpr int Oo = 64;
static constexpr int ROWS = Bb * Tt;

typedef unsigned long long ull;

// Scratch (device globals: allocation APIs are forbidden).
__device__ float g_gates[(size_t)ROWS * Gg];   // ~100 MB
__device__ float g_hs[(size_t)ROWS * Hh];      // ~25 MB

// ---- packed weights: staged in device mem, consumed from constant ----
struct PrepData {
    ull    wif[Hh * Ii];       // {W_ih[j][i],    W_ih[25+j][i]}   16B-aligned
    ull    wgo[Hh * Ii];       // {W_ih[50+j][i], W_ih[75+j][i]}
    ull    wfc[Hh * (Oo / 2)]; // [k][p] = {W_fc[2p][k], W_fc[2p+1][k]}
    ull    bfc[Oo / 2];        // {b_fc[2p], b_fc[2p+1]}
    float4 bias[Hh];           // {bi, bf, bg, bo} summed b_ih+b_hh
};
__device__   PrepData g_prep;
__constant__ PrepData c_w;

// ---- packed f32x2 helpers (sm_100+; ptxas never auto-fuses these) ----
__device__ __forceinline__ ull ffma2(ull a, ull b, ull c) {
    ull d;
    asm("fma.rn.f32x2 %0, %1, %2, %3;" : "=l"(d) : "l"(a), "l"(b), "l"(c));
    return d;
}
__device__ __forceinline__ ull fadd2(ull a, ull b) {
    ull d;
    asm("add.rn.f32x2 %0, %1, %2;" : "=l"(d) : "l"(a), "l"(b));
    return d;
}
__device__ __forceinline__ ull pack2(float lo, float hi) {
    ull r;
    asm("mov.b64 %0, {%1, %2};" : "=l"(r) : "f"(lo), "f"(hi));
    return r;
}
__device__ __forceinline__ float2 unpack2(ull v) {
    float2 r;
    asm("mov.b64 {%0, %1}, %2;" : "=f"(r.x), "=f"(r.y) : "l"(v));
    return r;
}
__device__ __forceinline__ float tanh_fast(float x) {
    float r;
    asm("tanh.approx.f32 %0, %1;" : "=f"(r) : "f"(x));
    return r;
}
// sigmoid(x) = 0.5*tanh(0.5x) + 0.5  — one MUFU instead of EX2+RCP.
__device__ __forceinline__ float sigmoid_fast(float x) {
    return fmaf(tanh_fast(0.5f * x), 0.5f, 0.5f);
}

// ---------------------------------------------------------------------------
// prep: build packed weight pairs + summed biases in device staging buffer.
// ---------------------------------------------------------------------------
__global__ __launch_bounds__(256) void prep_kernel(
    const float* __restrict__ W_ih,
    const float* __restrict__ b_ih,
    const float* __restrict__ b_hh,
    const float* __restrict__ W_fc,
    const float* __restrict__ b_fc)
{
    const int tid = threadIdx.x;
    for (int idx = tid; idx < Hh * Ii; idx += 256) {
        const int j = idx >> 6, i = idx & 63;
        g_prep.wif[idx] = pack2(W_ih[j * Ii + i],        W_ih[(25 + j) * Ii + i]);
        g_prep.wgo[idx] = pack2(W_ih[(50 + j) * Ii + i], W_ih[(75 + j) * Ii + i]);
    }
    for (int idx = tid; idx < Hh * (Oo / 2); idx += 256) {
        const int k = idx / (Oo / 2);
        const int p = idx % (Oo / 2);
        g_prep.wfc[idx] = pack2(W_fc[(2 * p) * Hh + k], W_fc[(2 * p + 1) * Hh + k]);
    }
    if (tid < Oo / 2) g_prep.bfc[tid] = pack2(b_fc[2 * tid], b_fc[2 * tid + 1]);
    if (tid < Hh)
        g_prep.bias[tid] = make_float4(b_ih[tid]      + b_hh[tid],
                                       b_ih[25 + tid] + b_hh[25 + tid],
                                       b_ih[50 + tid] + b_hh[50 + tid],
                                       b_ih[75 + tid] + b_hh[75 + tid]);
}

// ---------------------------------------------------------------------------
// Phase 1: one thread per (b,t) row; weights via uniform constant reads.
// ---------------------------------------------------------------------------
__global__ __launch_bounds__(128) void gates_kernel(
    const float* __restrict__ x)
{
    const int tid = threadIdx.x;
    const size_t row = (size_t)blockIdx.x * 128 + tid;

    ull xx[Ii];
    const float4* xp = (const float4*)(x + row * Ii);
#pragma unroll
    for (int i4 = 0; i4 < Ii / 4; ++i4) {
        const float4 v = xp[i4];
        xx[4 * i4 + 0] = pack2(v.x, v.x);
        xx[4 * i4 + 1] = pack2(v.y, v.y);
        xx[4 * i4 + 2] = pack2(v.z, v.z);
        xx[4 * i4 + 3] = pack2(v.w, v.w);
    }

    float4* gout = (float4*)(g_gates + row * Gg);

#pragma unroll 1
    for (int j = 0; j < Hh; ++j) {
        ull aif0 = 0ull, aif1 = 0ull, ago0 = 0ull, ago1 = 0ull;
        const ulonglong2* wi = (const ulonglong2*)&c_w.wif[j * Ii];
        const ulonglong2* wg = (const ulonglong2*)&c_w.wgo[j * Ii];
#pragma unroll
        for (int i2 = 0; i2 < Ii / 2; ++i2) {
            const ulonglong2 wv = wi[i2];
            const ulonglong2 wG = wg[i2];
            aif0 = ffma2(wv.x, xx[2 * i2 + 0], aif0);
            aif1 = ffma2(wv.y, xx[2 * i2 + 1], aif1);
            ago0 = ffma2(wG.x, xx[2 * i2 + 0], ago0);
            ago1 = ffma2(wG.y, xx[2 * i2 + 1], ago1);
        }
        const float2 fi0 = unpack2(aif0), fi1 = unpack2(aif1);
        const float2 fg0 = unpack2(ago0), fg1 = unpack2(ago1);
        const float4 b = c_w.bias[j];
        gout[j] = make_float4(fi0.x + fi1.x + b.x,
                              fi0.y + fi1.y + b.y,
                              fg0.x + fg1.x + b.z,
                              fg0.y + fg1.y + b.w);
    }
}

// ---------------------------------------------------------------------------
// Phase 2: one warp per TWO batch elements, shuffle-broadcast h, branch-free
// lanes (clamped indices), 4-deep prefetch per sequence, approx activations.
// ---------------------------------------------------------------------------
__global__ __launch_bounds__(32) void lstm_kernel(
    const float* __restrict__ W_hh)
{
    const int j  = threadIdx.x;
    const int jc = (j < Hh) ? j : (Hh - 1);
    const bool act = (j < Hh);
    const int bA = 2 * blockIdx.x;
    const int bB = bA + 1;

    // Recurrent weights packed (i,f)/(g,o), shared by both sequences.
    ull wif[Hh], wgo[Hh];
#pragma unroll
    for (int k = 0; k < Hh; ++k) {
        wif[k] = pack2(W_hh[jc * Hh + k],        W_hh[(25 + jc) * Hh + k]);
        wgo[k] = pack2(W_hh[(50 + jc) * Hh + k], W_hh[(75 + jc) * Hh + k]);
    }

    const float4* gpA = (const float4*)g_gates + (size_t)bA * Tt * Hh + jc;
    const float4* gpB = (const float4*)g_gates + (size_t)bB * Tt * Hh + jc;
    float* hpA = g_hs + (size_t)bA * Tt * Hh + j;
    float* hpB = g_hs + (size_t)bB * Tt * Hh + j;

    float hA = 0.0f, cA = 0.0f;
    float hB = 0.0f, cB = 0.0f;

    // Prefetch queues, depth 4 per sequence.
    float4 qA[4], qB[4];
#pragma unroll
    for (int d = 0; d < 4; ++d) {
        qA[d] = gpA[(size_t)d * Hh];
        qB[d] = gpB[(size_t)d * Hh];
    }

#pragma unroll 1
    for (int t = 0; t < Tt; t += 4) {
#pragma unroll
        for (int u = 0; u < 4; ++u) {
            const float4 gA = qA[u];
            const float4 gB = qB[u];
            if (t + 4 + u < Tt) {
                qA[u] = gpA[(size_t)(t + 4 + u) * Hh];
                qB[u] = gpB[(size_t)(t + 4 + u) * Hh];
            }

            // Interleaved dots: h @ W_hh^T for both sequences, 2-way split.
            ull aA0 = 0ull, aA1 = 0ull, dA0 = 0ull, dA1 = 0ull;
            ull aB0 = 0ull, aB1 = 0ull, dB0 = 0ull, dB1 = 0ull;
#pragma unroll
            for (int k = 0; k < Hh; ++k) {
                const float hkA = __shfl_sync(0xffffffffu, hA, k);
                const float hkB = __shfl_sync(0xffffffffu, hB, k);
                const ull h2A = pack2(hkA, hkA);
                const ull h2B = pack2(hkB, hkB);
                if (k & 1) {
                    aA1 = ffma2(wif[k], h2A, aA1);
                    aB1 = ffma2(wif[k], h2B, aB1);
                    dA1 = ffma2(wgo[k], h2A, dA1);
                    dB1 = ffma2(wgo[k], h2B, dB1);
                } else {
                    aA0 = ffma2(wif[k], h2A, aA0);
                    aB0 = ffma2(wif[k], h2B, aB0);
                    dA0 = ffma2(wgo[k], h2A, dA0);
                    dB0 = ffma2(wgo[k], h2B, dB0);
                }
            }

            // Sequence A update.
            {
                const float2 fif = unpack2(fadd2(aA0, aA1));
                const float2 fgo = unpack2(fadd2(dA0, dA1));
                const float iv = sigmoid_fast(gA.x + fif.x);
                const float fv = sigmoid_fast(gA.y + fif.y);
                const float gv = tanh_fast   (gA.z + fgo.x);
                const float ov = sigmoid_fast(gA.w + fgo.y);
                cA = fv * cA + iv * gv;
                const float hn = ov * tanh_fast(cA);
                hA = act ? hn : 0.0f;
                if (act) hpA[(size_t)(t + u) * Hh] = hn;
            }
            // Sequence B update.
            {
                const float2 fif = unpack2(fadd2(aB0, aB1));
                const float2 fgo = unpack2(fadd2(dB0, dB1));
                const float iv = sigmoid_fast(gB.x + fif.x);
                const float fv = sigmoid_fast(gB.y + fif.y);
                const float gv = tanh_fast   (gB.z + fgo.x);
                const float ov = sigmoid_fast(gB.w + fgo.y);
                cB = fv * cB + iv * gv;
                const float hn = ov * tanh_fast(cB);
                hB = act ? hn : 0.0f;
                if (act) hpB[(size_t)(t + u) * Hh] = hn;
            }
        }
    }
}

// ---------------------------------------------------------------------------
// Phase 3: out[row][o] = b_fc[o] + sum_k hs[row][k] * W_fc[o][k]
// One thread per row; weights via uniform constant reads.
// ---------------------------------------------------------------------------
__global__ __launch_bounds__(128) void fc_kernel(
    float* __restrict__ out)
{
    const int tid = threadIdx.x;
    const size_t row = (size_t)blockIdx.x * 128 + tid;
    const float* hp = g_hs + row * Hh;

    float hv[Hh];
#pragma unroll
    for (int k = 0; k < Hh; ++k) hv[k] = hp[k];

    ull acc[Oo / 2];
#pragma unroll
    for (int p = 0; p < Oo / 2; ++p) acc[p] = c_w.bfc[p];

#pragma unroll 1
    for (int k = 0; k < Hh; ++k) {
        const ull h2 = pack2(hv[k], hv[k]);
        const ulonglong2* wv = (const ulonglong2*)&c_w.wfc[k * (Oo / 2)];
#pragma unroll
        for (int p2 = 0; p2 < Oo / 4; ++p2) {
            const ulonglong2 w = wv[p2];
            acc[2 * p2 + 0] = ffma2(w.x, h2, acc[2 * p2 + 0]);
            acc[2 * p2 + 1] = ffma2(w.y, h2, acc[2 * p2 + 1]);
        }
    }

    float4* op = (float4*)(out + row * Oo);
#pragma unroll
    for (int p4 = 0; p4 < Oo / 4; ++p4) {
        const float2 a = unpack2(acc[2 * p4]);
        const float2 b = unpack2(acc[2 * p4 + 1]);
        op[p4] = make_float4(a.x, a.y, b.x, b.y);
    }
}

// ---------------------------------------------------------------------------
extern "C" void kernel_launch(void* const* d_in, const int* in_sizes, int n_in,
                              void* d_out, int out_size)
{
    const float* x    = (const float*)d_in[0];
    const float* W_ih = (const float*)d_in[1];
    const float* W_hh = (const float*)d_in[2];
    const float* b_ih = (const float*)d_in[3];
    const float* b_hh = (const float*)d_in[4];
    const float* W_fc = (const float*)d_in[5];
    const float* b_fc = (const float*)d_in[6];
    float* out = (float*)d_out;

    prep_kernel<<<1, 256>>>(W_ih, b_ih, b_hh, W_fc, b_fc);

    void* prep_addr = nullptr;
    cudaGetSymbolAddress(&prep_addr, g_prep);
    cudaMemcpyToSymbolAsync(c_w, prep_addr, sizeof(PrepData), 0,
                            cudaMemcpyDeviceToDevice, 0);

    gates_kernel<<<ROWS / 128, 128>>>(x);
    lstm_kernel<<<Bb / 2, 32>>>(W_hh);
    fc_kernel<<<ROWS / 128, 128>>>(out);
}

// round 13
// speedup vs baseline: 2.4567x; 2.4567x over previous
#include <cuda_runtime.h>

// ImprovedRNN (LSTM) B=256, T=1024, I=64, H=25, O=64, fp32.
// Gate order (PyTorch): i, f, g, o = rows 0..24, 25..49, 50..74, 75..99.
//
// R10 = R6 (best known: 437us) + single-MUFU sigmoid in lstm_kernel.
// Phase 1 (gates_kernel): gates_x = x @ W_ih^T + (b_ih+b_hh), interleaved
//   layout g_gates[row*25 + j] = float4{ i_j, f_j, g_j, o_j }, FFMA2-packed,
//   weights pre-paired in shared (measured 133.6us, LDS-wavefront-bound).
// Phase 2 (lstm_kernel): one warp per batch element, branch-free lanes,
//   shuffle h-broadcast, 4-deep gate prefetch, ALL activations via a single
//   tanh.approx MUFU (sigma(x) = 0.5*tanh(0.5x)+0.5).
// Phase 3 (fc_kernel): out = hs @ W_fc^T + b_fc (measured ~40us).

static constexpr int Bb = 256;
static constexpr int Tt = 1024;
static constexpr int Ii = 64;
static constexpr int Hh = 25;
static constexpr int Gg = 4 * Hh;   // 100
static constexpr int Oo = 64;
static constexpr int ROWS = Bb * Tt;

typedef unsigned long long ull;

// Scratch (device globals: allocation APIs are forbidden).
__device__ float g_gates[(size_t)ROWS * Gg];   // ~100 MB
__device__ float g_hs[(size_t)ROWS * Hh];      // ~25 MB

// ---- packed f32x2 helpers (sm_100+; ptxas never auto-fuses these) ----
__device__ __forceinline__ ull ffma2(ull a, ull b, ull c) {
    ull d;
    asm("fma.rn.f32x2 %0, %1, %2, %3;" : "=l"(d) : "l"(a), "l"(b), "l"(c));
    return d;
}
__device__ __forceinline__ ull fadd2(ull a, ull b) {
    ull d;
    asm("add.rn.f32x2 %0, %1, %2;" : "=l"(d) : "l"(a), "l"(b));
    return d;
}
__device__ __forceinline__ ull pack2(float lo, float hi) {
    ull r;
    asm("mov.b64 %0, {%1, %2};" : "=l"(r) : "f"(lo), "f"(hi));
    return r;
}
__device__ __forceinline__ float2 unpack2(ull v) {
    float2 r;
    asm("mov.b64 {%0, %1}, %2;" : "=f"(r.x), "=f"(r.y) : "l"(v));
    return r;
}
__device__ __forceinline__ float tanh_fast(float x) {
    float r;
    asm("tanh.approx.f32 %0, %1;" : "=f"(r) : "f"(x));
    return r;
}
// sigmoid(x) = 0.5*tanh(0.5x) + 0.5 — one MUFU instead of EX2+RCP.
__device__ __forceinline__ float sigmoid_fast(float x) {
    return fmaf(tanh_fast(0.5f * x), 0.5f, 0.5f);
}

// ---------------------------------------------------------------------------
// Phase 1: one thread per (b,t) row. x row packed {xi,xi} in registers,
// W_ih pre-paired (i,f)/(g,o) in shared. 3200 FFMA2 per row.
// ---------------------------------------------------------------------------
__global__ __launch_bounds__(128) void gates_kernel(
    const float* __restrict__ x,
    const float* __restrict__ W_ih,
    const float* __restrict__ b_ih,
    const float* __restrict__ b_hh)
{
    __shared__ ull Wif2[Hh * Ii];    // {W_ih[j][i], W_ih[25+j][i]}
    __shared__ ull Wgo2[Hh * Ii];    // {W_ih[50+j][i], W_ih[75+j][i]}
    __shared__ float4 bsh[Hh];

    const int tid = threadIdx.x;
    for (int idx = tid; idx < Hh * Ii; idx += 128) {
        const int j = idx >> 6, i = idx & 63;
        Wif2[idx] = pack2(W_ih[j * Ii + i],        W_ih[(25 + j) * Ii + i]);
        Wgo2[idx] = pack2(W_ih[(50 + j) * Ii + i], W_ih[(75 + j) * Ii + i]);
    }
    if (tid < Hh)
        bsh[tid] = make_float4(b_ih[tid]      + b_hh[tid],
                               b_ih[25 + tid] + b_hh[25 + tid],
                               b_ih[50 + tid] + b_hh[50 + tid],
                               b_ih[75 + tid] + b_hh[75 + tid]);
    __syncthreads();

    const size_t row = (size_t)blockIdx.x * 128 + tid;

    ull xx[Ii];
    const float4* xp = (const float4*)(x + row * Ii);
#pragma unroll
    for (int i4 = 0; i4 < Ii / 4; ++i4) {
        const float4 v = xp[i4];
        xx[4 * i4 + 0] = pack2(v.x, v.x);
        xx[4 * i4 + 1] = pack2(v.y, v.y);
        xx[4 * i4 + 2] = pack2(v.z, v.z);
        xx[4 * i4 + 3] = pack2(v.w, v.w);
    }

    float4* gout = (float4*)(g_gates + row * Gg);

#pragma unroll 1
    for (int j = 0; j < Hh; ++j) {
        ull aif0 = 0ull, aif1 = 0ull, ago0 = 0ull, ago1 = 0ull;
        const ull* wi = &Wif2[j * Ii];
        const ull* wg = &Wgo2[j * Ii];
#pragma unroll
        for (int i = 0; i < Ii; i += 2) {
            aif0 = ffma2(wi[i],     xx[i],     aif0);
            aif1 = ffma2(wi[i + 1], xx[i + 1], aif1);
            ago0 = ffma2(wg[i],     xx[i],     ago0);
            ago1 = ffma2(wg[i + 1], xx[i + 1], ago1);
        }
        const float2 fi0 = unpack2(aif0), fi1 = unpack2(aif1);
        const float2 fg0 = unpack2(ago0), fg1 = unpack2(ago1);
        const float4 b = bsh[j];
        gout[j] = make_float4(fi0.x + fi1.x + b.x,
                              fi0.y + fi1.y + b.y,
                              fg0.x + fg1.x + b.z,
                              fg0.y + fg1.y + b.w);
    }
}

// ---------------------------------------------------------------------------
// Phase 2: one warp per batch element. Lane j (<25) owns hidden unit j;
// lanes 25-31 run uniformly with clamped indices (stores predicated).
// 4-step prefetch queue hides DRAM latency of the gate stream.
// ---------------------------------------------------------------------------
__global__ __launch_bounds__(32) void lstm_kernel(
    const float* __restrict__ W_hh)
{
    const int j  = threadIdx.x;
    const int jc = (j < Hh) ? j : (Hh - 1);   // clamped lane index
    const bool act = (j < Hh);
    const int b = blockIdx.x;

    // Recurrent weights packed (i,f)/(g,o) per k (clamped lanes dup row 24).
    ull wif[Hh], wgo[Hh];
#pragma unroll
    for (int k = 0; k < Hh; ++k) {
        wif[k] = pack2(W_hh[jc * Hh + k],        W_hh[(25 + jc) * Hh + k]);
        wgo[k] = pack2(W_hh[(50 + jc) * Hh + k], W_hh[(75 + jc) * Hh + k]);
    }

    const float4* gp = (const float4*)g_gates + (size_t)b * Tt * Hh + jc;
    float* hp = g_hs + (size_t)b * Tt * Hh + j;

    float h = 0.0f, c = 0.0f;

    // Prefetch queue, depth 4.
    float4 q[4];
#pragma unroll
    for (int d = 0; d < 4; ++d) q[d] = gp[(size_t)d * Hh];

#pragma unroll 1
    for (int t = 0; t < Tt; t += 4) {
#pragma unroll
        for (int u = 0; u < 4; ++u) {
            const float4 g = q[u];
            if (t + 4 + u < Tt) q[u] = gp[(size_t)(t + 4 + u) * Hh];

            // h @ W_hh^T : 4-way split accumulators per gate pair.
            ull a0 = 0ull, a1 = 0ull, a2 = 0ull, a3 = 0ull;   // (i,f)
            ull d0 = 0ull, d1 = 0ull, d2 = 0ull, d3 = 0ull;   // (g,o)
#pragma unroll
            for (int k = 0; k < Hh; ++k) {
                const float hk = __shfl_sync(0xffffffffu, h, k);
                const ull h2 = pack2(hk, hk);
                switch (k & 3) {
                    case 0: a0 = ffma2(wif[k], h2, a0); d0 = ffma2(wgo[k], h2, d0); break;
                    case 1: a1 = ffma2(wif[k], h2, a1); d1 = ffma2(wgo[k], h2, d1); break;
                    case 2: a2 = ffma2(wif[k], h2, a2); d2 = ffma2(wgo[k], h2, d2); break;
                    default: a3 = ffma2(wif[k], h2, a3); d3 = ffma2(wgo[k], h2, d3); break;
                }
            }
            const ull aif = fadd2(fadd2(a0, a1), fadd2(a2, a3));
            const ull ago = fadd2(fadd2(d0, d1), fadd2(d2, d3));

            const float2 fif = unpack2(aif);
            const float2 fgo = unpack2(ago);
            const float iv = sigmoid_fast(g.x + fif.x);
            const float fv = sigmoid_fast(g.y + fif.y);
            const float gv = tanh_fast   (g.z + fgo.x);
            const float ov = sigmoid_fast(g.w + fgo.y);

            c = fv * c + iv * gv;
            const float hn = ov * tanh_fast(c);
            h = act ? hn : 0.0f;
            if (act) hp[(size_t)(t + u) * Hh] = hn;   // predicated store
        }
    }
}

// ---------------------------------------------------------------------------
// Phase 3: out[row][o] = b_fc[o] + sum_k hs[row][k] * W_fc[o][k]
// One thread per row; W_fc transposed+paired in shared, FFMA2 accumulation.
// ---------------------------------------------------------------------------
__global__ __launch_bounds__(128) void fc_kernel(
    const float* __restrict__ W_fc,
    const float* __restrict__ b_fc,
    float* __restrict__ out)
{
    __shared__ ull Wt2[Hh * (Oo / 2)];   // {W_fc[2p][k], W_fc[2p+1][k]}
    __shared__ ull bsh2[Oo / 2];

    const int tid = threadIdx.x;
    for (int idx = tid; idx < Hh * (Oo / 2); idx += 128) {
        const int k = idx / (Oo / 2);
        const int p = idx % (Oo / 2);
        Wt2[idx] = pack2(W_fc[(2 * p) * Hh + k], W_fc[(2 * p + 1) * Hh + k]);
    }
    if (tid < Oo / 2) bsh2[tid] = pack2(b_fc[2 * tid], b_fc[2 * tid + 1]);
    __syncthreads();

    const size_t row = (size_t)blockIdx.x * 128 + tid;
    const float* hp = g_hs + row * Hh;

    float hv[Hh];
#pragma unroll
    for (int k = 0; k < Hh; ++k) hv[k] = hp[k];

    ull acc[Oo / 2];
#pragma unroll
    for (int p = 0; p < Oo / 2; ++p) acc[p] = bsh2[p];

#pragma unroll 1
    for (int k = 0; k < Hh; ++k) {
        const ull h2 = pack2(hv[k], hv[k]);
        const ull* wv = &Wt2[k * (Oo / 2)];
#pragma unroll
        for (int p = 0; p < Oo / 2; ++p)
            acc[p] = ffma2(wv[p], h2, acc[p]);
    }

    float4* op = (float4*)(out + row * Oo);
#pragma unroll
    for (int p4 = 0; p4 < Oo / 4; ++p4) {
        const float2 a = unpack2(acc[2 * p4]);
        const float2 b = unpack2(acc[2 * p4 + 1]);
        op[p4] = make_float4(a.x, a.y, b.x, b.y);
    }
}

// ---------------------------------------------------------------------------
extern "C" void kernel_launch(void* const* d_in, const int* in_sizes, int n_in,
                              void* d_out, int out_size)
{
    const float* x    = (const float*)d_in[0];
    const float* W_ih = (const float*)d_in[1];
    const float* W_hh = (const float*)d_in[2];
    const float* b_ih = (const float*)d_in[3];
    const float* b_hh = (const float*)d_in[4];
    const float* W_fc = (const float*)d_in[5];
    const float* b_fc = (const float*)d_in[6];
    float* out = (float*)d_out;

    gates_kernel<<<ROWS / 128, 128>>>(x, W_ih, b_ih, b_hh);
    lstm_kernel<<<Bb, 32>>>(W_hh);
    fc_kernel<<<ROWS / 128, 128>>>(W_fc, b_fc, out);
}